// round 13
// baseline (speedup 1.0000x reference)
#include <cuda_runtime.h>
#include <cuda_fp16.h>
#include <math.h>

#define N_NODES 500000
#define N_EDGES 3000000
#define FULLMASK 0xFFFFFFFFu

#define SCAN_ITEMS 8
#define SCAN_BS 256
#define SCAN_CHUNK (SCAN_ITEMS * SCAN_BS)                     // 2048
#define SCAN_NBLK ((N_NODES + SCAN_CHUNK - 1) / SCAN_CHUNK)   // 245

// ---- device scratch (no allocations allowed) ----
__device__ int    g_deg[N_NODES];
__device__ int    g_off[N_NODES];
__device__ int    g_cur[N_NODES];
__device__ int    g_esrc[N_EDGES];      // src per edge, sorted by dst
__device__ int    g_edst[N_EDGES];      // dst per edge, sorted (runs of equal d)
__device__ int    g_bsum[SCAN_NBLK], g_bpre[SCAN_NBLK];
__device__ float  g_h1[N_NODES * 16];   // layer-1 accumulator (atomic target)
__device__ float  g_p[N_NODES * 16];    // p_i = x_i@(A1-A2)+b1a  (fp32 64B row)
__device__ __half g_v[N_NODES * 16];    // v_j = x_j@A2           (fp16 32B row)
__device__ float4 g_q[N_NODES];         // q_i = b2a + h_i@(Wtop-Wbot)
__device__ float4 g_r[N_NODES];         // r_j = h_j@Wbot

// float atomic-max via signed/unsigned bit trick (exact, order-independent)
__device__ __forceinline__ void atomic_max_float(float* addr, float v) {
    if (v >= 0.f) atomicMax((int*)addr, __float_as_int(v));
    else          atomicMin((unsigned int*)addr, __float_as_uint(v));
}

// 256-bit load of 8 consecutive 32-bit words (Blackwell LDG.E.256)
__device__ __forceinline__ void ld256(const float* p, float* v) {
#if defined(__CUDA_ARCH__) && (__CUDA_ARCH__ >= 1000)
    asm volatile(
        "ld.global.v8.f32 {%0, %1, %2, %3, %4, %5, %6, %7}, [%8];"
        : "=f"(v[0]), "=f"(v[1]), "=f"(v[2]), "=f"(v[3]),
          "=f"(v[4]), "=f"(v[5]), "=f"(v[6]), "=f"(v[7])
        : "l"(p));
#else
    const float4* p4 = (const float4*)p;
    float4 a = p4[0], b = p4[1];
    v[0] = a.x; v[1] = a.y; v[2] = a.z; v[3] = a.w;
    v[4] = b.x; v[5] = b.y; v[6] = b.z; v[7] = b.w;
#endif
}

// ---- packed dual-lane fp32 FMA ----
#if defined(__CUDA_ARCH__) && (__CUDA_ARCH__ >= 1000)
#define HAVE_F32X2 1
__device__ __forceinline__ unsigned long long pk2(float lo, float hi) {
    unsigned long long r;
    asm("mov.b64 %0, {%1, %2};" : "=l"(r) : "f"(lo), "f"(hi));
    return r;
}
__device__ __forceinline__ void upk2(unsigned long long v, float& lo, float& hi) {
    asm("mov.b64 {%0, %1}, %2;" : "=f"(lo), "=f"(hi) : "l"(v));
}
__device__ __forceinline__ void fma2(unsigned long long& d,
                                     unsigned long long a, unsigned long long b) {
    asm("fma.rn.f32x2 %0, %1, %2, %0;" : "+l"(d) : "l"(a), "l"(b));
}
#else
#define HAVE_F32X2 0
#endif

// ---------------------------------------------------------------------------
// K0: zero deg + h1, out <- -inf.
__global__ void init_kernel(float4* __restrict__ out4) {
    int i = blockIdx.x * blockDim.x + threadIdx.x;
    int stride = gridDim.x * blockDim.x;
    for (int j = i; j < N_NODES; j += stride) g_deg[j] = 0;
    float4* a = (float4*)g_h1;
    const float4 z = make_float4(0.f, 0.f, 0.f, 0.f);
    for (int j = i; j < N_NODES * 4; j += stride) a[j] = z;
    const float NI = __int_as_float(0xFF800000);
    const float4 ni = make_float4(NI, NI, NI, NI);
    for (int j = i; j < N_NODES; j += stride) out4[j] = ni;
}

// K1: in-degree histogram
__global__ void __launch_bounds__(256) hist_kernel(const int* __restrict__ ei) {
    int e = blockIdx.x * 256 + threadIdx.x;
    if (e >= N_EDGES) return;
    atomicAdd(&g_deg[ei[N_EDGES + e]], 1);
}

// K2-K4: exclusive scan deg -> off (and cur)
__global__ void __launch_bounds__(SCAN_BS) scan1_kernel() {
    __shared__ int sh[SCAN_BS];
    int b = blockIdx.x, t = threadIdx.x;
    int base = b * SCAN_CHUNK + t * SCAN_ITEMS;
    int sum = 0;
#pragma unroll
    for (int k = 0; k < SCAN_ITEMS; k++) {
        int i = base + k;
        if (i < N_NODES) sum += g_deg[i];
    }
    sh[t] = sum; __syncthreads();
    for (int off = 128; off > 0; off >>= 1) {
        if (t < off) sh[t] += sh[t + off];
        __syncthreads();
    }
    if (t == 0) g_bsum[b] = sh[0];
}
__global__ void __launch_bounds__(SCAN_BS) scan2_kernel() {
    __shared__ int sh[SCAN_BS];
    int t = threadIdx.x;
    int v = (t < SCAN_NBLK) ? g_bsum[t] : 0;
    sh[t] = v; __syncthreads();
    for (int off = 1; off < SCAN_BS; off <<= 1) {
        int tmp = (t >= off) ? sh[t - off] : 0;
        __syncthreads();
        sh[t] += tmp;
        __syncthreads();
    }
    if (t < SCAN_NBLK) g_bpre[t] = sh[t] - v;
}
__global__ void __launch_bounds__(SCAN_BS) scan3_kernel() {
    __shared__ int sh[SCAN_BS];
    int b = blockIdx.x, t = threadIdx.x;
    int base = b * SCAN_CHUNK + t * SCAN_ITEMS;
    int vals[SCAN_ITEMS];
    int tsum = 0;
#pragma unroll
    for (int k = 0; k < SCAN_ITEMS; k++) {
        int i = base + k;
        vals[k] = (i < N_NODES) ? g_deg[i] : 0;
        tsum += vals[k];
    }
    sh[t] = tsum; __syncthreads();
    for (int off = 1; off < SCAN_BS; off <<= 1) {
        int tmp = (t >= off) ? sh[t - off] : 0;
        __syncthreads();
        sh[t] += tmp;
        __syncthreads();
    }
    int running = g_bpre[b] + sh[t] - tsum;
#pragma unroll
    for (int k = 0; k < SCAN_ITEMS; k++) {
        int i = base + k;
        if (i < N_NODES) { g_off[i] = running; g_cur[i] = running; }
        running += vals[k];
    }
}

// K5: fill dst array coalesced from offsets
__global__ void __launch_bounds__(256) fill_dst_kernel() {
    int i = blockIdx.x * 256 + threadIdx.x;
    if (i >= N_NODES) return;
    int o = g_off[i], dg = g_deg[i];
    for (int j = 0; j < dg; j++) g_edst[o + j] = i;
}

// K6: scatter src into dst-grouped slots
__global__ void __launch_bounds__(256) scatter_kernel(const int* __restrict__ ei) {
    int e = blockIdx.x * 256 + threadIdx.x;
    if (e >= N_EDGES) return;
    int s = ei[e];
    int d = ei[N_EDGES + e];
    int slot = atomicAdd(&g_cur[d], 1);
    g_esrc[slot] = s;
}

// K7: per-node p (fp32) and v (fp16) from x and w1a
__global__ void __launch_bounds__(256) pv_kernel(
    const float* __restrict__ x,
    const float* __restrict__ w1a, const float* __restrict__ b1a) {
    __shared__ float sw[96], sb[16];
    int t = threadIdx.x;
    if (t < 96) sw[t] = w1a[t];
    if (t < 16) sb[t] = b1a[t];
    __syncthreads();
    int i = blockIdx.x * 256 + t;
    if (i >= N_NODES) return;
    float x0 = x[3 * i], x1 = x[3 * i + 1], x2 = x[3 * i + 2];
    float p[16]; __half vh[16];
#pragma unroll
    for (int k = 0; k < 16; k++) {
        float v = x0 * sw[48 + k] + x1 * sw[64 + k] + x2 * sw[80 + k];    // x@A2
        float pp = sb[k] + x0 * (sw[k] - sw[48 + k]) + x1 * (sw[16 + k] - sw[64 + k])
                 + x2 * (sw[32 + k] - sw[80 + k]);                         // x@(A1-A2)+b
        p[k] = pp; vh[k] = __float2half_rn(v);
    }
    float4* pd = (float4*)(g_p + (long long)i * 16);
    const float4* ps = (const float4*)p;
#pragma unroll
    for (int q = 0; q < 4; q++) pd[q] = ps[q];
    uint4* vd = (uint4*)g_v;
    const uint4* vs = (const uint4*)vh;
    vd[2 * i] = vs[0]; vd[2 * i + 1] = vs[1];
}

// ---------------------------------------------------------------------------
// K8: edge1 on sorted edges. z = relu(p[d] + v[s]); outv = z@W1b + b1b;
// warp-segmented max over equal-d runs; leaders probe + filtered atomicMax.
// ---------------------------------------------------------------------------
__global__ void __launch_bounds__(256) edge1_kernel(
    const float* __restrict__ w1b, const float* __restrict__ b1b) {
    __shared__ float sw[256], sb[16];
    int t = threadIdx.x;
    sw[t] = w1b[t];
    if (t < 16) sb[t] = b1b[t];
    __syncthreads();

    int e = blockIdx.x * 256 + t;
    if (e >= N_EDGES) return;       // exits in whole warps (3M % 32 == 0)
    int d = g_edst[e];              // coalesced
    int s = g_esrc[e];              // coalesced

    float p[16];
    ld256(g_p + (long long)d * 16, p);          // coalesced (sorted d)
    ld256(g_p + (long long)d * 16 + 8, p + 8);
    float vraw[8];
    ld256((const float*)(g_v + (long long)s * 16), vraw);   // 1 scattered wf

    float z[16];
#pragma unroll
    for (int q = 0; q < 8; q++) {
        unsigned u = __float_as_uint(vraw[q]);
        __half2 h = *reinterpret_cast<__half2*>(&u);
        float2 f = __half22float2(h);
        z[2 * q]     = fmaxf(p[2 * q] + f.x, 0.f);
        z[2 * q + 1] = fmaxf(p[2 * q + 1] + f.y, 0.f);
    }

    float outv[16];
#if HAVE_F32X2
    unsigned long long acc[8];
#pragma unroll
    for (int q = 0; q < 8; q++) acc[q] = pk2(sb[2 * q], sb[2 * q + 1]);
#pragma unroll
    for (int c = 0; c < 16; c++) {
        unsigned long long zc = pk2(z[c], z[c]);
        const float* wr = &sw[c * 16];
#pragma unroll
        for (int q = 0; q < 8; q++)
            fma2(acc[q], zc, pk2(wr[2 * q], wr[2 * q + 1]));
    }
#pragma unroll
    for (int q = 0; q < 8; q++) upk2(acc[q], outv[2 * q], outv[2 * q + 1]);
#else
#pragma unroll
    for (int k = 0; k < 16; k++) {
        float a = sb[k];
#pragma unroll
        for (int c = 0; c < 16; c++) a = fmaf(z[c], sw[c * 16 + k], a);
        outv[k] = a;
    }
#endif

    // Warp-segmented max over contiguous equal-d runs (sorted => contiguous)
    int lane = t & 31;
#pragma unroll
    for (int st = 1; st < 32; st <<= 1) {
        int nd = __shfl_down_sync(FULLMASK, d, st);
        bool same = (lane + st < 32) && (nd == d);
#pragma unroll
        for (int k = 0; k < 16; k++) {
            float nv = __shfl_down_sync(FULLMASK, outv[k], st);
            if (same) outv[k] = fmaxf(outv[k], nv);
        }
    }
    int pd = __shfl_up_sync(FULLMASK, d, 1);
    bool leader = (lane == 0) || (pd != d);

    if (leader) {
        float* dstp = g_h1 + (long long)d * 16;
        float cur[16];
        ld256(dstp, cur);
        ld256(dstp + 8, cur + 8);
#pragma unroll
        for (int k = 0; k < 16; k++) {
            if (outv[k] > 0.f && outv[k] > cur[k])
                atomicMax((int*)(dstp + k), __float_as_int(outv[k]));
        }
    }
}

// K9: per-node factoring of layer 2's first GEMM
__global__ void __launch_bounds__(256) qr_kernel(
    const float* __restrict__ w2a, const float* __restrict__ b2a) {
    __shared__ float sw[128], sb[4];
    int t = threadIdx.x;
    if (t < 128) sw[t] = w2a[t];
    if (t < 4)   sb[t] = b2a[t];
    __syncthreads();
    int i = blockIdx.x * 256 + t;
    if (i >= N_NODES) return;
    float h[16];
    const float4* hp = (const float4*)(g_h1 + (long long)i * 16);
#pragma unroll
    for (int q = 0; q < 4; q++) {
        float4 c = hp[q];
        h[4 * q] = c.x; h[4 * q + 1] = c.y; h[4 * q + 2] = c.z; h[4 * q + 3] = c.w;
    }
    float q[4], r[4];
#pragma unroll
    for (int n = 0; n < 4; n++) {
        float aq = sb[n], ar = 0.f;
#pragma unroll
        for (int c = 0; c < 16; c++) {
            float wb = sw[(16 + c) * 4 + n];
            aq = fmaf(h[c], sw[c * 4 + n] - wb, aq);
            ar = fmaf(h[c], wb, ar);
        }
        q[n] = aq; r[n] = ar;
    }
    g_q[i] = make_float4(q[0], q[1], q[2], q[3]);
    g_r[i] = make_float4(r[0], r[1], r[2], r[3]);
}

// ---------------------------------------------------------------------------
// K10: edge2 on sorted edges, factored + segmented.
// ---------------------------------------------------------------------------
__global__ void __launch_bounds__(256) edge2_kernel(
    const float* __restrict__ w2b, const float* __restrict__ b2b,
    float* __restrict__ out) {
    __shared__ float sw[16], sb[4];
    int t = threadIdx.x;
    if (t < 16) sw[t] = w2b[t];
    if (t < 4)  sb[t] = b2b[t];
    __syncthreads();

    int e = blockIdx.x * 256 + t;
    if (e >= N_EDGES) return;
    int d = g_edst[e];
    int s = g_esrc[e];

    float4 qv = g_q[d];            // coalesced (sorted d)
    float4 rv = __ldg(&g_r[s]);    // 1 scattered wf
    float z[4] = {fmaxf(qv.x + rv.x, 0.f), fmaxf(qv.y + rv.y, 0.f),
                  fmaxf(qv.z + rv.z, 0.f), fmaxf(qv.w + rv.w, 0.f)};
    float ov[4];
#pragma unroll
    for (int k = 0; k < 4; k++) {
        float a = sb[k];
#pragma unroll
        for (int j = 0; j < 4; j++) a = fmaf(z[j], sw[j * 4 + k], a);
        ov[k] = a;
    }

    int lane = t & 31;
#pragma unroll
    for (int st = 1; st < 32; st <<= 1) {
        int nd = __shfl_down_sync(FULLMASK, d, st);
        bool same = (lane + st < 32) && (nd == d);
#pragma unroll
        for (int k = 0; k < 4; k++) {
            float nv = __shfl_down_sync(FULLMASK, ov[k], st);
            if (same) ov[k] = fmaxf(ov[k], nv);
        }
    }
    int pd = __shfl_up_sync(FULLMASK, d, 1);
    bool leader = (lane == 0) || (pd != d);

    if (leader) {
        float* dstp = out + (long long)d * 4;
        float4 c = *((const float4*)dstp);
        float cur[4] = {c.x, c.y, c.z, c.w};
#pragma unroll
        for (int k = 0; k < 4; k++) {
            if (!(ov[k] <= cur[k]))
                atomic_max_float(dstp + k, ov[k]);
        }
    }
}

// K11: finalize: -inf -> 0, log_softmax
__global__ void __launch_bounds__(256) finalize_kernel(float4* __restrict__ out4) {
    int i = blockIdx.x * 256 + threadIdx.x;
    if (i >= N_NODES) return;
    float4 v = out4[i];
    if (!isfinite(v.x)) v.x = 0.f;
    if (!isfinite(v.y)) v.y = 0.f;
    if (!isfinite(v.z)) v.z = 0.f;
    if (!isfinite(v.w)) v.w = 0.f;
    float m = fmaxf(fmaxf(v.x, v.y), fmaxf(v.z, v.w));
    float s = expf(v.x - m) + expf(v.y - m) + expf(v.z - m) + expf(v.w - m);
    float l = m + logf(s);
    v.x -= l; v.y -= l; v.z -= l; v.w -= l;
    out4[i] = v;
}

extern "C" void kernel_launch(void* const* d_in, const int* in_sizes, int n_in,
                              void* d_out, int out_size) {
    const float* x   = (const float*)d_in[0];
    const int*   ei  = (const int*)d_in[1];
    const float* w1a = (const float*)d_in[2];
    const float* b1a = (const float*)d_in[3];
    const float* w1b = (const float*)d_in[4];
    const float* b1b = (const float*)d_in[5];
    const float* w2a = (const float*)d_in[6];
    const float* b2a = (const float*)d_in[7];
    const float* w2b = (const float*)d_in[8];
    const float* b2b = (const float*)d_in[9];
    float* out = (float*)d_out;

    int eb = (N_EDGES + 255) / 256;
    int nb = (N_NODES + 255) / 256;

    init_kernel<<<2048, 256>>>((float4*)out);
    hist_kernel<<<eb, 256>>>(ei);
    scan1_kernel<<<SCAN_NBLK, SCAN_BS>>>();
    scan2_kernel<<<1, SCAN_BS>>>();
    scan3_kernel<<<SCAN_NBLK, SCAN_BS>>>();
    fill_dst_kernel<<<nb, 256>>>();
    scatter_kernel<<<eb, 256>>>(ei);
    pv_kernel<<<nb, 256>>>(x, w1a, b1a);
    edge1_kernel<<<eb, 256>>>(w1b, b1b);
    qr_kernel<<<nb, 256>>>(w2a, b2a);
    edge2_kernel<<<eb, 256>>>(w2b, b2b, out);
    finalize_kernel<<<nb, 256>>>((float4*)out);
}

// round 14
// speedup vs baseline: 1.1842x; 1.1842x over previous
#include <cuda_runtime.h>
#include <math.h>

#define N_NODES 500000
#define N_EDGES 3000000

// Scratch buffers (device globals — no allocation allowed)
__device__ float  g_h1[N_NODES * 16];   // layer-1 fp32 accumulator (atomic target)
__device__ float4 g_x4[N_NODES];        // padded x for single-load gathers
__device__ float4 g_q[N_NODES];         // q_i = b2a + h_i@(Wtop-Wbot)
__device__ float4 g_r[N_NODES];         // r_j = h_j@Wbot

// ---------------------------------------------------------------------------
// Kernel 0: pack x -> float4 table, zero g_h1.
// ---------------------------------------------------------------------------
__global__ void init_kernel(const float* __restrict__ x) {
    int i = blockIdx.x * blockDim.x + threadIdx.x;
    int stride = gridDim.x * blockDim.x;
    for (int j = i; j < N_NODES; j += stride)
        g_x4[j] = make_float4(x[3 * j], x[3 * j + 1], x[3 * j + 2], 0.f);
    float4* a = (float4*)g_h1;
    const float4 z = make_float4(0.f, 0.f, 0.f, 0.f);
    for (int j = i; j < N_NODES * 4; j += stride) a[j] = z;
}

// float atomic-max via signed/unsigned bit trick (exact, order-independent)
__device__ __forceinline__ void atomic_max_float(float* addr, float v) {
    if (v >= 0.f) atomicMax((int*)addr, __float_as_int(v));
    else          atomicMin((unsigned int*)addr, __float_as_uint(v));
}

// 256-bit load of 8 consecutive floats (Blackwell LDG.E.256).
__device__ __forceinline__ void ld256(const float* p, float* v) {
#if defined(__CUDA_ARCH__) && (__CUDA_ARCH__ >= 1000)
    asm volatile(
        "ld.global.v8.f32 {%0, %1, %2, %3, %4, %5, %6, %7}, [%8];"
        : "=f"(v[0]), "=f"(v[1]), "=f"(v[2]), "=f"(v[3]),
          "=f"(v[4]), "=f"(v[5]), "=f"(v[6]), "=f"(v[7])
        : "l"(p));
#else
    const float4* p4 = (const float4*)p;
    float4 a = p4[0], b = p4[1];
    v[0] = a.x; v[1] = a.y; v[2] = a.z; v[3] = a.w;
    v[4] = b.x; v[5] = b.y; v[6] = b.z; v[7] = b.w;
#endif
}

// ---- packed dual-lane fp32 FMA (sm_100a FFMA2; ptxas won't emit from C++) ----
#if defined(__CUDA_ARCH__) && (__CUDA_ARCH__ >= 1000)
#define HAVE_F32X2 1
__device__ __forceinline__ unsigned long long pk2(float lo, float hi) {
    unsigned long long r;
    asm("mov.b64 %0, {%1, %2};" : "=l"(r) : "f"(lo), "f"(hi));
    return r;
}
__device__ __forceinline__ void upk2(unsigned long long v, float& lo, float& hi) {
    asm("mov.b64 {%0, %1}, %2;" : "=f"(lo), "=f"(hi) : "l"(v));
}
__device__ __forceinline__ void fma2(unsigned long long& d,
                                     unsigned long long a, unsigned long long b) {
    asm("fma.rn.f32x2 %0, %1, %2, %0;" : "+l"(d) : "l"(a), "l"(b));
}
#else
#define HAVE_F32X2 0
#endif

// ---------------------------------------------------------------------------
// Kernel 1: EdgeConv layer 1.  g_x4 -> scatter-max into g_h1[N,16].
// Probe loads hoisted above the GEMMs (latency hides under FMA work);
// GEMMs run on packed f32x2 lanes (half the FMA issues, bit-exact fp32).
// ---------------------------------------------------------------------------
__global__ void __launch_bounds__(256) edge1_kernel(
    const int* __restrict__ ei,
    const float* __restrict__ w1a, const float* __restrict__ b1a,
    const float* __restrict__ w1b, const float* __restrict__ b1b) {
    __shared__ float sw1a[96], sb1a[16], sw1b[256], sb1b[16];
    int t = threadIdx.x;
    if (t < 96)  sw1a[t] = w1a[t];
    if (t < 16)  { sb1a[t] = b1a[t]; sb1b[t] = b1b[t]; }
    sw1b[t] = w1b[t];                   // blockDim == 256
    __syncthreads();

    int e = blockIdx.x * 256 + t;
    if (e >= N_EDGES) return;
    int s = ei[e];
    int d = ei[N_EDGES + e];

    // Hoisted probe: issue the accumulator-row loads NOW; ~250cyc of L2
    // latency overlaps with the gathers + both GEMMs below. Stale-safe.
    float* dstp = g_h1 + (long long)d * 16;
    float cur[16];
    ld256(dstp, cur);
    ld256(dstp + 8, cur + 8);

    float4 xi = __ldg(&g_x4[d]);
    float4 xj = __ldg(&g_x4[s]);
    float in6[6] = {xi.x, xi.y, xi.z, xj.x - xi.x, xj.y - xi.y, xj.z - xi.z};

#if HAVE_F32X2
    // GEMM 1 (6x16) on 8 packed accumulators
    unsigned long long acc[8];
#pragma unroll
    for (int p = 0; p < 8; p++) acc[p] = pk2(sb1a[2 * p], sb1a[2 * p + 1]);
#pragma unroll
    for (int c = 0; c < 6; c++) {
        unsigned long long zc = pk2(in6[c], in6[c]);
        const float* wr = &sw1a[c * 16];
#pragma unroll
        for (int p = 0; p < 8; p++)
            fma2(acc[p], zc, pk2(wr[2 * p], wr[2 * p + 1]));
    }
    float hid[16];
#pragma unroll
    for (int p = 0; p < 8; p++) {
        float lo, hi; upk2(acc[p], lo, hi);
        hid[2 * p] = fmaxf(lo, 0.f); hid[2 * p + 1] = fmaxf(hi, 0.f);
    }
    // GEMM 2 (16x16) on 8 packed accumulators
    unsigned long long acc2[8];
#pragma unroll
    for (int p = 0; p < 8; p++) acc2[p] = pk2(sb1b[2 * p], sb1b[2 * p + 1]);
#pragma unroll
    for (int c = 0; c < 16; c++) {
        unsigned long long zc = pk2(hid[c], hid[c]);
        const float* wr = &sw1b[c * 16];
#pragma unroll
        for (int p = 0; p < 8; p++)
            fma2(acc2[p], zc, pk2(wr[2 * p], wr[2 * p + 1]));
    }
    float outv[16];
#pragma unroll
    for (int p = 0; p < 8; p++) upk2(acc2[p], outv[2 * p], outv[2 * p + 1]);
#else
    float hid[16];
#pragma unroll
    for (int k = 0; k < 16; k++) {
        float a = sb1a[k];
#pragma unroll
        for (int c = 0; c < 6; c++) a = fmaf(in6[c], sw1a[c * 16 + k], a);
        hid[k] = fmaxf(a, 0.f);
    }
    float outv[16];
#pragma unroll
    for (int k = 0; k < 16; k++) {
        float a = sb1b[k];
#pragma unroll
        for (int j = 0; j < 16; j++) a = fmaf(hid[j], sw1b[j * 16 + k], a);
        outv[k] = a;
    }
#endif

#pragma unroll
    for (int k = 0; k < 16; k++) {
        // init 0 => non-positive can't win; stale cur => extra RED, still correct
        if (outv[k] > 0.f && outv[k] > cur[k])
            atomicMax((int*)(dstp + k), __float_as_int(outv[k]));
    }
}

// ---------------------------------------------------------------------------
// Kernel 1.5: per-node factoring of layer 2's first GEMM (coalesced) and
// out <- -inf init (folded here: runs right before edge2 anyway).
// q_i = b2a + h_i@(Wtop - Wbot),  r_i = h_i@Wbot.
// ---------------------------------------------------------------------------
__global__ void __launch_bounds__(256) qr_kernel(
    const float* __restrict__ w2a, const float* __restrict__ b2a,
    float4* __restrict__ out4) {
    __shared__ float sw[128], sb[4];
    int t = threadIdx.x;
    if (t < 128) sw[t] = w2a[t];
    if (t < 4)   sb[t] = b2a[t];
    __syncthreads();
    int i = blockIdx.x * 256 + t;
    if (i >= N_NODES) return;

    const float NI = __int_as_float(0xFF800000);
    out4[i] = make_float4(NI, NI, NI, NI);

    float h[16];
    const float4* hp = (const float4*)(g_h1 + (long long)i * 16);
#pragma unroll
    for (int q = 0; q < 4; q++) {
        float4 c = hp[q];
        h[4 * q] = c.x; h[4 * q + 1] = c.y; h[4 * q + 2] = c.z; h[4 * q + 3] = c.w;
    }

    float q[4], r[4];
#pragma unroll
    for (int n = 0; n < 4; n++) {
        float aq = sb[n], ar = 0.f;
#pragma unroll
        for (int c = 0; c < 16; c++) {
            float wb = sw[(16 + c) * 4 + n];           // Wbot[c][n]
            aq = fmaf(h[c], sw[c * 4 + n] - wb, aq);   // h@(Wtop-Wbot)
            ar = fmaf(h[c], wb, ar);                   // h@Wbot
        }
        q[n] = aq; r[n] = ar;
    }
    g_q[i] = make_float4(q[0], q[1], q[2], q[3]);
    g_r[i] = make_float4(r[0], r[1], r[2], r[3]);
}

// ---------------------------------------------------------------------------
// Kernel 2: EdgeConv layer 2, factored.  3 wavefronts/edge:
// q[d] gather + r[s] gather + out probe. z4=relu(q+r); out=z4@W2b+b2b; max.
// (s==d self-loops are handled naturally: q_i + r_i == b2a + h_i@Wtop.)
// ---------------------------------------------------------------------------
__global__ void __launch_bounds__(256) edge2_kernel(
    const int* __restrict__ ei,
    const float* __restrict__ w2b, const float* __restrict__ b2b,
    float* __restrict__ out) {
    __shared__ float sw[16], sb[4];
    int t = threadIdx.x;
    if (t < 16) sw[t] = w2b[t];
    if (t < 4)  sb[t] = b2b[t];
    __syncthreads();

    int e = blockIdx.x * 256 + t;
    if (e >= N_EDGES) return;
    int s = ei[e];
    int d = ei[N_EDGES + e];

    // Hoist probe load before compute (stale-safe)
    float* dstp = out + (long long)d * 4;
    float4 c = *((const float4*)dstp);

    float4 qv = __ldg(&g_q[d]);
    float4 rv = __ldg(&g_r[s]);
    float z[4] = {fmaxf(qv.x + rv.x, 0.f), fmaxf(qv.y + rv.y, 0.f),
                  fmaxf(qv.z + rv.z, 0.f), fmaxf(qv.w + rv.w, 0.f)};

    float ov[4];
#pragma unroll
    for (int k = 0; k < 4; k++) {
        float a = sb[k];
#pragma unroll
        for (int j = 0; j < 4; j++) a = fmaf(z[j], sw[j * 4 + k], a);
        ov[k] = a;
    }

    float cur[4] = {c.x, c.y, c.z, c.w};
#pragma unroll
    for (int k = 0; k < 4; k++) {
        if (!(ov[k] <= cur[k]))
            atomic_max_float(dstp + k, ov[k]);
    }
}

// ---------------------------------------------------------------------------
// Kernel 3: finalize.  -inf -> 0, then log_softmax over the 4 channels.
// ---------------------------------------------------------------------------
__global__ void __launch_bounds__(256) finalize_kernel(float4* __restrict__ out4) {
    int i = blockIdx.x * 256 + threadIdx.x;
    if (i >= N_NODES) return;
    float4 v = out4[i];
    if (!isfinite(v.x)) v.x = 0.f;
    if (!isfinite(v.y)) v.y = 0.f;
    if (!isfinite(v.z)) v.z = 0.f;
    if (!isfinite(v.w)) v.w = 0.f;
    float m = fmaxf(fmaxf(v.x, v.y), fmaxf(v.z, v.w));
    float s = expf(v.x - m) + expf(v.y - m) + expf(v.z - m) + expf(v.w - m);
    float l = m + logf(s);
    v.x -= l; v.y -= l; v.z -= l; v.w -= l;
    out4[i] = v;
}

extern "C" void kernel_launch(void* const* d_in, const int* in_sizes, int n_in,
                              void* d_out, int out_size) {
    const float* x   = (const float*)d_in[0];
    const int*   ei  = (const int*)d_in[1];
    const float* w1a = (const float*)d_in[2];
    const float* b1a = (const float*)d_in[3];
    const float* w1b = (const float*)d_in[4];
    const float* b1b = (const float*)d_in[5];
    const float* w2a = (const float*)d_in[6];
    const float* b2a = (const float*)d_in[7];
    const float* w2b = (const float*)d_in[8];
    const float* b2b = (const float*)d_in[9];
    float* out = (float*)d_out;

    init_kernel<<<2048, 256>>>(x);
    int eb = (N_EDGES + 255) / 256;
    int nb = (N_NODES + 255) / 256;
    edge1_kernel<<<eb, 256>>>(ei, w1a, b1a, w1b, b1b);
    qr_kernel<<<nb, 256>>>(w2a, b2a, (float4*)out);
    edge2_kernel<<<eb, 256>>>(ei, w2b, b2b, out);
    finalize_kernel<<<nb, 256>>>((float4*)out);
}

// round 15
// speedup vs baseline: 1.2264x; 1.0356x over previous
#include <cuda_runtime.h>
#include <math.h>

#define N_NODES 500000
#define N_EDGES 3000000
#define FULLMASK 0xFFFFFFFFu

// Scratch buffers (device globals — no allocation allowed)
__device__ float  g_h1[N_NODES * 16];   // layer-1 fp32 accumulator (atomic target)
__device__ float4 g_x4[N_NODES];        // padded x for single-load gathers
__device__ float4 g_q[N_NODES];         // q_i = b2a + h_i@(Wtop-Wbot)
__device__ float4 g_r[N_NODES];         // r_j = h_j@Wbot

// ---------------------------------------------------------------------------
// Kernel 0: pack x -> float4 table, zero g_h1.
// ---------------------------------------------------------------------------
__global__ void init_kernel(const float* __restrict__ x) {
    int i = blockIdx.x * blockDim.x + threadIdx.x;
    int stride = gridDim.x * blockDim.x;
    for (int j = i; j < N_NODES; j += stride)
        g_x4[j] = make_float4(x[3 * j], x[3 * j + 1], x[3 * j + 2], 0.f);
    float4* a = (float4*)g_h1;
    const float4 z = make_float4(0.f, 0.f, 0.f, 0.f);
    for (int j = i; j < N_NODES * 4; j += stride) a[j] = z;
}

// float atomic-max via signed/unsigned bit trick (exact, order-independent)
__device__ __forceinline__ void atomic_max_float(float* addr, float v) {
    if (v >= 0.f) atomicMax((int*)addr, __float_as_int(v));
    else          atomicMin((unsigned int*)addr, __float_as_uint(v));
}

// 256-bit load of 8 consecutive floats (Blackwell LDG.E.256).
__device__ __forceinline__ void ld256(const float* p, float* v) {
#if defined(__CUDA_ARCH__) && (__CUDA_ARCH__ >= 1000)
    asm volatile(
        "ld.global.v8.f32 {%0, %1, %2, %3, %4, %5, %6, %7}, [%8];"
        : "=f"(v[0]), "=f"(v[1]), "=f"(v[2]), "=f"(v[3]),
          "=f"(v[4]), "=f"(v[5]), "=f"(v[6]), "=f"(v[7])
        : "l"(p));
#else
    const float4* p4 = (const float4*)p;
    float4 a = p4[0], b = p4[1];
    v[0] = a.x; v[1] = a.y; v[2] = a.z; v[3] = a.w;
    v[4] = b.x; v[5] = b.y; v[6] = b.z; v[7] = b.w;
#endif
}

// ---- packed dual-lane fp32 FMA (sm_100a FFMA2; ptxas won't emit from C++) ----
#if defined(__CUDA_ARCH__) && (__CUDA_ARCH__ >= 1000)
#define HAVE_F32X2 1
__device__ __forceinline__ unsigned long long pk2(float lo, float hi) {
    unsigned long long r;
    asm("mov.b64 %0, {%1, %2};" : "=l"(r) : "f"(lo), "f"(hi));
    return r;
}
__device__ __forceinline__ void upk2(unsigned long long v, float& lo, float& hi) {
    asm("mov.b64 {%0, %1}, %2;" : "=f"(lo), "=f"(hi) : "l"(v));
}
__device__ __forceinline__ void fma2(unsigned long long& d,
                                     unsigned long long a, unsigned long long b) {
    asm("fma.rn.f32x2 %0, %1, %2, %0;" : "+l"(d) : "l"(a), "l"(b));
}
#else
#define HAVE_F32X2 0
#endif

// ---------------------------------------------------------------------------
// Kernel 1: EdgeConv layer 1.  g_x4 -> scatter-max into g_h1[N,16].
// Pair-cooperative probe: lane pairs split each 64B accumulator row (one
// 128B line) so both probe instructions touch 16 lines each -> 1 wf/edge
// instead of 2. Probes stale-safe; atomicMax is the correctness guard.
// ---------------------------------------------------------------------------
__global__ void __launch_bounds__(256) edge1_kernel(
    const int* __restrict__ ei,
    const float* __restrict__ w1a, const float* __restrict__ b1a,
    const float* __restrict__ w1b, const float* __restrict__ b1b) {
    __shared__ float sw1a[96], sb1a[16], sw1b[256], sb1b[16];
    int t = threadIdx.x;
    if (t < 96)  sw1a[t] = w1a[t];
    if (t < 16)  { sb1a[t] = b1a[t]; sb1b[t] = b1b[t]; }
    sw1b[t] = w1b[t];                   // blockDim == 256
    __syncthreads();

    int e = blockIdx.x * 256 + t;
    if (e >= N_EDGES) return;           // exits in whole warps (3M % 32 == 0)
    int lane = t & 31;
    int s = ei[e];
    int d = ei[N_EDGES + e];

    // ---- pair-cooperative probe issue (hoisted; latency hides under GEMMs) --
    // Partner's d; instr A covers even-lane edges' rows, instr B odd-lane's.
    int dpair = __shfl_xor_sync(FULLMASK, d, 1);
    int odd = lane & 1;
    int dA = odd ? dpair : d;    // even edge's dst
    int dB = odd ? d : dpair;    // odd edge's dst
    float A[8], B[8];
    ld256(g_h1 + (long long)dA * 16 + odd * 8, A);   // 16 lines / 32 lanes
    ld256(g_h1 + (long long)dB * 16 + odd * 8, B);   // 16 lines / 32 lanes

    float4 xi = __ldg(&g_x4[d]);
    float4 xj = __ldg(&g_x4[s]);
    float in6[6] = {xi.x, xi.y, xi.z, xj.x - xi.x, xj.y - xi.y, xj.z - xi.z};

#if HAVE_F32X2
    // GEMM 1 (6x16) on 8 packed accumulators
    unsigned long long acc[8];
#pragma unroll
    for (int p = 0; p < 8; p++) acc[p] = pk2(sb1a[2 * p], sb1a[2 * p + 1]);
#pragma unroll
    for (int c = 0; c < 6; c++) {
        unsigned long long zc = pk2(in6[c], in6[c]);
        const float* wr = &sw1a[c * 16];
#pragma unroll
        for (int p = 0; p < 8; p++)
            fma2(acc[p], zc, pk2(wr[2 * p], wr[2 * p + 1]));
    }
    float hid[16];
#pragma unroll
    for (int p = 0; p < 8; p++) {
        float lo, hi; upk2(acc[p], lo, hi);
        hid[2 * p] = fmaxf(lo, 0.f); hid[2 * p + 1] = fmaxf(hi, 0.f);
    }
    // GEMM 2 (16x16) on 8 packed accumulators
    unsigned long long acc2[8];
#pragma unroll
    for (int p = 0; p < 8; p++) acc2[p] = pk2(sb1b[2 * p], sb1b[2 * p + 1]);
#pragma unroll
    for (int c = 0; c < 16; c++) {
        unsigned long long zc = pk2(hid[c], hid[c]);
        const float* wr = &sw1b[c * 16];
#pragma unroll
        for (int p = 0; p < 8; p++)
            fma2(acc2[p], zc, pk2(wr[2 * p], wr[2 * p + 1]));
    }
    float outv[16];
#pragma unroll
    for (int p = 0; p < 8; p++) upk2(acc2[p], outv[2 * p], outv[2 * p + 1]);
#else
    float hid[16];
#pragma unroll
    for (int k = 0; k < 16; k++) {
        float a = sb1a[k];
#pragma unroll
        for (int c = 0; c < 6; c++) a = fmaf(in6[c], sw1a[c * 16 + k], a);
        hid[k] = fmaxf(a, 0.f);
    }
    float outv[16];
#pragma unroll
    for (int k = 0; k < 16; k++) {
        float a = sb1b[k];
#pragma unroll
        for (int j = 0; j < 16; j++) a = fmaf(hid[j], sw1b[j * 16 + k], a);
        outv[k] = a;
    }
#endif

    // ---- redistribute probe halves (16 shfl) --------------------------------
    // Even lane owns edge: low = own A, high = partner's A.
    // Odd lane owns edge:  low = partner's B, high = own B.
    float curlo[8], curhi[8];
#pragma unroll
    for (int i = 0; i < 8; i++) {
        float xA = __shfl_xor_sync(FULLMASK, A[i], 1);
        float xB = __shfl_xor_sync(FULLMASK, B[i], 1);
        curlo[i] = odd ? xB : A[i];
        curhi[i] = odd ? B[i] : xA;
    }

    float* dstp = g_h1 + (long long)d * 16;
#pragma unroll
    for (int k = 0; k < 8; k++) {
        // init 0 => non-positive can't win; stale cur => extra RED, still correct
        if (outv[k] > 0.f && outv[k] > curlo[k])
            atomicMax((int*)(dstp + k), __float_as_int(outv[k]));
    }
#pragma unroll
    for (int k = 0; k < 8; k++) {
        if (outv[8 + k] > 0.f && outv[8 + k] > curhi[k])
            atomicMax((int*)(dstp + 8 + k), __float_as_int(outv[8 + k]));
    }
}

// ---------------------------------------------------------------------------
// Kernel 1.5: per-node factoring of layer 2's first GEMM (coalesced) and
// out <- -inf init (folded here: runs right before edge2 anyway).
// q_i = b2a + h_i@(Wtop - Wbot),  r_i = h_i@Wbot.
// ---------------------------------------------------------------------------
__global__ void __launch_bounds__(256) qr_kernel(
    const float* __restrict__ w2a, const float* __restrict__ b2a,
    float4* __restrict__ out4) {
    __shared__ float sw[128], sb[4];
    int t = threadIdx.x;
    if (t < 128) sw[t] = w2a[t];
    if (t < 4)   sb[t] = b2a[t];
    __syncthreads();
    int i = blockIdx.x * 256 + t;
    if (i >= N_NODES) return;

    const float NI = __int_as_float(0xFF800000);
    out4[i] = make_float4(NI, NI, NI, NI);

    float h[16];
    const float4* hp = (const float4*)(g_h1 + (long long)i * 16);
#pragma unroll
    for (int q = 0; q < 4; q++) {
        float4 c = hp[q];
        h[4 * q] = c.x; h[4 * q + 1] = c.y; h[4 * q + 2] = c.z; h[4 * q + 3] = c.w;
    }

    float q[4], r[4];
#pragma unroll
    for (int n = 0; n < 4; n++) {
        float aq = sb[n], ar = 0.f;
#pragma unroll
        for (int c = 0; c < 16; c++) {
            float wb = sw[(16 + c) * 4 + n];           // Wbot[c][n]
            aq = fmaf(h[c], sw[c * 4 + n] - wb, aq);   // h@(Wtop-Wbot)
            ar = fmaf(h[c], wb, ar);                   // h@Wbot
        }
        q[n] = aq; r[n] = ar;
    }
    g_q[i] = make_float4(q[0], q[1], q[2], q[3]);
    g_r[i] = make_float4(r[0], r[1], r[2], r[3]);
}

// ---------------------------------------------------------------------------
// Kernel 2: EdgeConv layer 2, factored.  3 wavefronts/edge:
// q[d] gather + r[s] gather + out probe. z4=relu(q+r); out=z4@W2b+b2b; max.
// (s==d self-loops are handled naturally: q_i + r_i == b2a + h_i@Wtop.)
// ---------------------------------------------------------------------------
__global__ void __launch_bounds__(256) edge2_kernel(
    const int* __restrict__ ei,
    const float* __restrict__ w2b, const float* __restrict__ b2b,
    float* __restrict__ out) {
    __shared__ float sw[16], sb[4];
    int t = threadIdx.x;
    if (t < 16) sw[t] = w2b[t];
    if (t < 4)  sb[t] = b2b[t];
    __syncthreads();

    int e = blockIdx.x * 256 + t;
    if (e >= N_EDGES) return;
    int s = ei[e];
    int d = ei[N_EDGES + e];

    // Hoist probe load before compute (stale-safe)
    float* dstp = out + (long long)d * 4;
    float4 c = *((const float4*)dstp);

    float4 qv = __ldg(&g_q[d]);
    float4 rv = __ldg(&g_r[s]);
    float z[4] = {fmaxf(qv.x + rv.x, 0.f), fmaxf(qv.y + rv.y, 0.f),
                  fmaxf(qv.z + rv.z, 0.f), fmaxf(qv.w + rv.w, 0.f)};

    float ov[4];
#pragma unroll
    for (int k = 0; k < 4; k++) {
        float a = sb[k];
#pragma unroll
        for (int j = 0; j < 4; j++) a = fmaf(z[j], sw[j * 4 + k], a);
        ov[k] = a;
    }

    float cur[4] = {c.x, c.y, c.z, c.w};
#pragma unroll
    for (int k = 0; k < 4; k++) {
        if (!(ov[k] <= cur[k]))
            atomic_max_float(dstp + k, ov[k]);
    }
}

// ---------------------------------------------------------------------------
// Kernel 3: finalize.  -inf -> 0, then log_softmax over the 4 channels.
// ---------------------------------------------------------------------------
__global__ void __launch_bounds__(256) finalize_kernel(float4* __restrict__ out4) {
    int i = blockIdx.x * 256 + threadIdx.x;
    if (i >= N_NODES) return;
    float4 v = out4[i];
    if (!isfinite(v.x)) v.x = 0.f;
    if (!isfinite(v.y)) v.y = 0.f;
    if (!isfinite(v.z)) v.z = 0.f;
    if (!isfinite(v.w)) v.w = 0.f;
    float m = fmaxf(fmaxf(v.x, v.y), fmaxf(v.z, v.w));
    float s = expf(v.x - m) + expf(v.y - m) + expf(v.z - m) + expf(v.w - m);
    float l = m + logf(s);
    v.x -= l; v.y -= l; v.z -= l; v.w -= l;
    out4[i] = v;
}

extern "C" void kernel_launch(void* const* d_in, const int* in_sizes, int n_in,
                              void* d_out, int out_size) {
    const float* x   = (const float*)d_in[0];
    const int*   ei  = (const int*)d_in[1];
    const float* w1a = (const float*)d_in[2];
    const float* b1a = (const float*)d_in[3];
    const float* w1b = (const float*)d_in[4];
    const float* b1b = (const float*)d_in[5];
    const float* w2a = (const float*)d_in[6];
    const float* b2a = (const float*)d_in[7];
    const float* w2b = (const float*)d_in[8];
    const float* b2b = (const float*)d_in[9];
    float* out = (float*)d_out;

    init_kernel<<<2048, 256>>>(x);
    int eb = (N_EDGES + 255) / 256;
    int nb = (N_NODES + 255) / 256;
    edge1_kernel<<<eb, 256>>>(ei, w1a, b1a, w1b, b1b);
    qr_kernel<<<nb, 256>>>(w2a, b2a, (float4*)out);
    edge2_kernel<<<eb, 256>>>(ei, w2b, b2b, out);
    finalize_kernel<<<nb, 256>>>((float4*)out);
}